// round 6
// baseline (speedup 1.0000x reference)
#include <cuda_runtime.h>
#include <cuda_bf16.h>
#include <stdint.h>

#define LN_EPS 1e-5f

namespace {
constexpr int TILE   = 512;    // columns per chunk
constexpr int NTHR   = 256;
constexpr int ZROWS  = 48;
constexpr int P1MAX  = 2048;   // max pass1 CTAs (persistent cap)
constexpr int GRAM_E = 1024;
constexpr int UE     = 48;
constexpr int PART_STRIDE = GRAM_E + UE;   // 1072
constexpr int MAXN   = 1 << 21;            // msv capacity (cols)
constexpr int WPITCH = 520;    // pass3 smem pitch (words per rowpair row)
}

// ---- scratch (allocation-free: __device__ globals) ----
__device__ float g_part[P1MAX * PART_STRIDE];
__device__ float g_gram[GRAM_E];
__device__ float g_u[UE];
__device__ __align__(16) __nv_bfloat16 g_A[64 * 32];
__device__ float g_e[64];
__device__ float g_rs[64];
__device__ __align__(16) float2 g_msv[MAXN];   // (mu, rv) per column

__device__ __forceinline__ void mma_m16n8k16(
    float& d0, float& d1, float& d2, float& d3,
    uint32_t a0, uint32_t a1, uint32_t a2, uint32_t a3,
    uint32_t b0, uint32_t b1)
{
    asm volatile(
        "mma.sync.aligned.m16n8k16.row.col.f32.bf16.bf16.f32 "
        "{%0,%1,%2,%3}, {%4,%5,%6,%7}, {%8,%9}, {%0,%1,%2,%3};\n"
        : "+f"(d0), "+f"(d1), "+f"(d2), "+f"(d3)
        : "r"(a0), "r"(a1), "r"(a2), "r"(a3), "r"(b0), "r"(b1));
}

__device__ __forceinline__ uint32_t pack_bf16(float lo, float hi) {
    __nv_bfloat162 b = __floats2bfloat162_rn(lo, hi);
    return *reinterpret_cast<uint32_t*>(&b);
}
__device__ __forceinline__ float bf_lo(uint32_t u) {
    __nv_bfloat162 b = *reinterpret_cast<__nv_bfloat162*>(&u);
    return __bfloat162float(b.x);
}
__device__ __forceinline__ float bf_hi(uint32_t u) {
    __nv_bfloat162 b = *reinterpret_cast<__nv_bfloat162*>(&u);
    return __bfloat162float(b.y);
}

// ============================================================================
// Pass 1: row-major streaming loads; per-column stats (saved to g_msv);
// normalized bf16 Z in smem; 32x32 Gram (rows [0,32) x [16,48)) + u[48]
// Zs word layout: word(r, wc) = r*256 + ((wc + 4r) & 255); word = cols (2wc,2wc+1)
// Static smem: 48KB exactly (no aux array; partner stats via shfl).
// ============================================================================
__global__ __launch_bounds__(NTHR, 4) void k_pass1(const float* __restrict__ x,
                                                   int N, int nchunks)
{
    __shared__ uint32_t Zs32[ZROWS * 256];   // 48KB
    __nv_bfloat16* zh = reinterpret_cast<__nv_bfloat16*>(Zs32);

    const int tid  = threadIdx.x;
    const int warp = tid >> 5;
    const int lane = tid & 31;
    const int g4   = lane >> 2;
    const int t4   = lane & 3;
    const int m_off = (warp >> 2) << 4;   // 0/16
    const int n_off = (warp & 3) << 3;    // 0,8,16,24
    const int cq   = tid >> 1;            // column quad (4 cols), partner = lane^1
    const int rh   = tid & 1;             // row parity

    float d0 = 0.f, d1 = 0.f, d2 = 0.f, d3 = 0.f;
    float ured[6] = {0.f, 0.f, 0.f, 0.f, 0.f, 0.f};

    for (int chunk = blockIdx.x; chunk < nchunks; chunk += gridDim.x) {
        const long col0 = (long)chunk * TILE;
        const bool fast = (col0 + TILE <= (long)N) && ((N & 3) == 0);

        if (fast) {
            // ---- phase A: 32 independent LDG.128, fixed-column accumulation
            const float* xp = x + col0 + 4 * cq;
            float s1[4] = {0.f, 0.f, 0.f, 0.f};
            float s2[4] = {0.f, 0.f, 0.f, 0.f};
#pragma unroll
            for (int k = 0; k < 32; k++) {
                const int r = 2 * k + rh;
                float4 v = __ldg(reinterpret_cast<const float4*>(xp + (size_t)r * N));
                s1[0] += v.x; s1[1] += v.y; s1[2] += v.z; s1[3] += v.w;
                s2[0] = fmaf(v.x, v.x, s2[0]);
                s2[1] = fmaf(v.y, v.y, s2[1]);
                s2[2] = fmaf(v.z, v.z, s2[2]);
                s2[3] = fmaf(v.w, v.w, s2[3]);
                if (k < 24) {   // r < 48 (static bound)
                    const int w0 = (2 * cq + 4 * r) & 255;   // even; +1 adjacent
                    uint64_t pk = (uint64_t)pack_bf16(v.x, v.y)
                                | ((uint64_t)pack_bf16(v.z, v.w) << 32);
                    *reinterpret_cast<uint64_t*>(&Zs32[r * 256 + w0]) = pk;
                }
            }
            // ---- partner stats exchange within warp (lane^1) ----
#pragma unroll
            for (int j = 0; j < 4; j++) {
                s1[j] += __shfl_xor_sync(0xffffffffu, s1[j], 1);
                s2[j] += __shfl_xor_sync(0xffffffffu, s2[j], 1);
            }
            if (!rh) {
                float mu[4], rv[4];
#pragma unroll
                for (int j = 0; j < 4; j++) {
                    mu[j] = s1[j] * (1.f / 64.f);
                    rv[j] = rsqrtf(s2[j] * (1.f / 64.f) - mu[j] * mu[j] + LN_EPS);
                }
                float4 st0 = make_float4(mu[0], rv[0], mu[1], rv[1]);
                float4 st1 = make_float4(mu[2], rv[2], mu[3], rv[3]);
                *reinterpret_cast<float4*>(&g_msv[col0 + 4 * cq])     = st0;
                *reinterpret_cast<float4*>(&g_msv[col0 + 4 * cq + 2]) = st1;
                // normalize own 4 columns, rows 0..47
#pragma unroll
                for (int r = 0; r < ZROWS; r++) {
                    const int wi = r * 256 + ((2 * cq + 4 * r) & 255);
                    uint64_t pk = *reinterpret_cast<uint64_t*>(&Zs32[wi]);
                    uint32_t w0 = (uint32_t)pk, w1 = (uint32_t)(pk >> 32);
                    float z0 = (bf_lo(w0) - mu[0]) * rv[0];
                    float z1 = (bf_hi(w0) - mu[1]) * rv[1];
                    float z2 = (bf_lo(w1) - mu[2]) * rv[2];
                    float z3 = (bf_hi(w1) - mu[3]) * rv[3];
                    *reinterpret_cast<uint64_t*>(&Zs32[wi]) =
                        (uint64_t)pack_bf16(z0, z1) | ((uint64_t)pack_bf16(z2, z3) << 32);
                }
            }
            __syncthreads();
        } else {
            // ---- scalar fallback: thread owns col pair (2*tid, 2*tid+1) ----
            const int wc = tid;  // word-col 0..255
            const long ca = col0 + 2 * wc, cb = ca + 1;
            float s1a = 0.f, s2a = 0.f, s1b = 0.f, s2b = 0.f;
#pragma unroll 1
            for (int r = 0; r < 64; r++) {
                float va = (ca < N) ? __ldg(x + (size_t)r * N + ca) : 0.f;
                float vb = (cb < N) ? __ldg(x + (size_t)r * N + cb) : 0.f;
                s1a += va; s2a = fmaf(va, va, s2a);
                s1b += vb; s2b = fmaf(vb, vb, s2b);
                if (r < ZROWS)
                    Zs32[r * 256 + ((wc + 4 * r) & 255)] = pack_bf16(va, vb);
            }
            const float mua = s1a * (1.f / 64.f);
            const float rva = rsqrtf(s2a * (1.f / 64.f) - mua * mua + LN_EPS);
            const float mub = s1b * (1.f / 64.f);
            const float rvb = rsqrtf(s2b * (1.f / 64.f) - mub * mub + LN_EPS);
            if (ca < N) g_msv[ca] = make_float2(mua, rva);
            if (cb < N) g_msv[cb] = make_float2(mub, rvb);
#pragma unroll 1
            for (int r = 0; r < ZROWS; r++) {
                const int wi = r * 256 + ((wc + 4 * r) & 255);
                uint32_t w = Zs32[wi];
                float za = (ca < N) ? (bf_lo(w) - mua) * rva : 0.f;
                float zb = (cb < N) ? (bf_hi(w) - mub) * rvb : 0.f;
                Zs32[wi] = pack_bf16(za, zb);
            }
            __syncthreads();
        }

        // ---- row sums u (8 warps x 6 rows), conflict-free ----
#pragma unroll
        for (int rr = 0; rr < 6; rr++) {
            const int row = warp + rr * 8;
            float s = 0.f;
#pragma unroll
            for (int i = 0; i < 8; i++) {
                uint32_t w = Zs32[row * 256 + ((lane + 32 * i + 4 * row) & 255)];
                s += bf_lo(w) + bf_hi(w);
            }
#pragma unroll
            for (int off = 16; off; off >>= 1)
                s += __shfl_xor_sync(0xffffffffu, s, off);
            ured[rr] += s;
        }

        // ---- Gram mma: D[32x32] += Z[0:32] * Z[16:48]^T over 512 columns ----
#pragma unroll 4
        for (int kk = 0; kk < 32; kk++) {
            const int k0 = kk * 16 + t4 * 2;
            const int ra = m_off + g4;
            const int rb = 16 + n_off + g4;
            uint32_t a0 = *reinterpret_cast<uint32_t*>(&zh[ra * TILE + ((k0 + 8 * ra) & 511)]);
            uint32_t a1 = *reinterpret_cast<uint32_t*>(&zh[(ra + 8) * TILE + ((k0 + 8 * (ra + 8)) & 511)]);
            uint32_t a2 = *reinterpret_cast<uint32_t*>(&zh[ra * TILE + ((k0 + 8 + 8 * ra) & 511)]);
            uint32_t a3 = *reinterpret_cast<uint32_t*>(&zh[(ra + 8) * TILE + ((k0 + 8 + 8 * (ra + 8)) & 511)]);
            uint32_t b0 = *reinterpret_cast<uint32_t*>(&zh[rb * TILE + ((k0 + 8 * rb) & 511)]);
            uint32_t b1 = *reinterpret_cast<uint32_t*>(&zh[rb * TILE + ((k0 + 8 + 8 * rb) & 511)]);
            mma_m16n8k16(d0, d1, d2, d3, a0, a1, a2, a3, b0, b1);
        }
        __syncthreads();
    }

    // ---- write deterministic per-CTA partials ----
    float* pp = g_part + (size_t)blockIdx.x * PART_STRIDE;
    const int row0 = m_off + g4;
    const int colp = n_off + t4 * 2;
    pp[row0 * 32 + colp]           = d0;
    pp[row0 * 32 + colp + 1]       = d1;
    pp[(row0 + 8) * 32 + colp]     = d2;
    pp[(row0 + 8) * 32 + colp + 1] = d3;
    if (lane == 0) {
#pragma unroll
        for (int rr = 0; rr < 6; rr++)
            pp[GRAM_E + warp + rr * 8] = ured[rr];
    }
}

// ============================================================================
// Reduce partials (deterministic)
// ============================================================================
__global__ void k_reduce(int nb)
{
    const int e = blockIdx.x * blockDim.x + threadIdx.x;
    if (e >= PART_STRIDE) return;
    float s = 0.f;
    int c = 0;
#pragma unroll 4
    for (; c + 4 <= nb; c += 4) {
        s += g_part[(size_t)c * PART_STRIDE + e]
           + g_part[(size_t)(c + 1) * PART_STRIDE + e]
           + g_part[(size_t)(c + 2) * PART_STRIDE + e]
           + g_part[(size_t)(c + 3) * PART_STRIDE + e];
    }
    for (; c < nb; c++) s += g_part[(size_t)c * PART_STRIDE + e];
    if (e < GRAM_E) g_gram[e] = s;
    else            g_u[e - GRAM_E] = s;
}

// ============================================================================
// Pass 2 (1 block, 64 threads): logits -> softmax -> A[64x32], e[64], rs[64]
// ============================================================================
__global__ void k_pass2(const float* __restrict__ gamma,
                        const float* __restrict__ beta,
                        const float* __restrict__ cw,
                        const float* __restrict__ cb,
                        float Nf)
{
    __shared__ float Gs[GRAM_E];
    __shared__ float us[UE];
    __shared__ float gs[64], bs[64];

    const int c = threadIdx.x;
    for (int i = c; i < GRAM_E; i += 64) Gs[i] = g_gram[i];
    if (c < UE) us[c] = g_u[c];
    gs[c] = gamma[c];
    bs[c] = beta[c];
    __syncthreads();

    const float wq = cw[c], bq = cb[c];
    const int   iq = c / 3;
    const float gi = gs[iq], bi = bs[iq], ui = us[iq];
    const float ti = gi * ui + Nf * bi;

    float L[64];
    float mx = -1e30f;
#pragma unroll 1
    for (int b2 = 0; b2 < 64; b2++) {
        const int   ik = (64 + b2) / 3;
        const float wk = cw[64 + b2], bk = cb[64 + b2];
        const float gj = gs[ik], bj = bs[ik], uj = us[ik];
        const float tj = gj * uj + Nf * bj;
        const float Gz = Gs[iq * 32 + (ik - 16)];
        const float S  = gi * gj * Gz + gi * bj * ui + bi * gj * uj + Nf * bi * bj;
        const float l  = 0.125f * (wq * wk * S + wq * bk * ti + bq * wk * tj + Nf * bq * bk);
        L[b2] = l;
        mx = fmaxf(mx, l);
    }
    float se = 0.f;
#pragma unroll 1
    for (int b2 = 0; b2 < 64; b2++) {
        const float ev = expf(L[b2] - mx);
        L[b2] = ev;
        se += ev;
    }
    const float inv = 1.f / se;

    float eacc = 0.f;
#pragma unroll 1
    for (int b2 = 0; b2 < 64; b2++) {
        L[b2] *= inv;
        eacc += L[b2] * cb[128 + b2];
    }

    float rssum = 0.f;
#pragma unroll 1
    for (int j = 32; j < 64; j++) {
        float P = 0.f;
        const int b0 = 3 * j - 128;
#pragma unroll
        for (int d = 0; d < 3; d++) {
            const int bb = b0 + d;
            if (bb >= 0 && bb < 64) P += L[bb] * cw[128 + bb];
        }
        const float Av = P * gs[j];
        const __nv_bfloat16 ab = __float2bfloat16(Av);
        g_A[c * 32 + (j - 32)] = ab;
        rssum += __bfloat162float(ab);
        eacc  += P * bs[j];
    }
    g_e[c]  = eacc;
    g_rs[c] = rssum;
}

// ============================================================================
// Pass 3: out = x + e + rv*(A@x[32:64] - mu*rs)
// phase A: row-pair float4 loads of rows 32..63 -> bf16 vertical pairs,
//          STS.128 into W[rowpair][col] (pitch 520 words, conflict-free)
// phase B: mma + residual + epilogue (stats come from g_msv)
// ============================================================================
__global__ __launch_bounds__(NTHR, 4) void k_pass3(const float* __restrict__ x,
                                                   float* __restrict__ out, int N)
{
    __shared__ uint32_t W[16 * WPITCH];   // 33.3KB
    __shared__ float2 msv[TILE];          // 4KB

    const int tid  = threadIdx.x;
    const int warp = tid >> 5;
    const int lane = tid & 31;
    const int g4   = lane >> 2;
    const int t4   = lane & 3;
    const int cq   = tid & 127;
    const int rh   = tid >> 7;

    const long col0 = (long)blockIdx.x * TILE;
    const bool fast = (col0 + TILE <= (long)N) && ((N & 3) == 0);

    if (fast) {
        const float* xp = x + col0 + 4 * cq;
#pragma unroll
        for (int k = 0; k < 8; k++) {
            const int rp = rh + 2 * k;               // 16 rowpairs across rh
            float4 va = __ldg(reinterpret_cast<const float4*>(xp + (size_t)(32 + 2 * rp) * N));
            float4 vb = __ldg(reinterpret_cast<const float4*>(xp + (size_t)(33 + 2 * rp) * N));
            uint4 wv;
            wv.x = pack_bf16(va.x, vb.x);
            wv.y = pack_bf16(va.y, vb.y);
            wv.z = pack_bf16(va.z, vb.z);
            wv.w = pack_bf16(va.w, vb.w);
            *reinterpret_cast<uint4*>(&W[rp * WPITCH + 4 * cq]) = wv;
        }
        msv[tid]       = g_msv[col0 + tid];
        msv[tid + 256] = g_msv[col0 + tid + 256];
    } else {
#pragma unroll 1
        for (int cc = 0; cc < 2; cc++) {
            const int lc = tid + 256 * cc;
            const long c = col0 + lc;
            if (c < N) {
#pragma unroll 1
                for (int rp = 0; rp < 16; rp++) {
                    float a = __ldg(x + (size_t)(32 + 2 * rp) * N + c);
                    float b = __ldg(x + (size_t)(33 + 2 * rp) * N + c);
                    W[rp * WPITCH + lc] = pack_bf16(a, b);
                }
                msv[lc] = g_msv[c];
            } else {
#pragma unroll 1
                for (int rp = 0; rp < 16; rp++) W[rp * WPITCH + lc] = 0u;
                msv[lc] = make_float2(0.f, 1.f);
            }
        }
    }
    __syncthreads();

    // ---- phase B: warp = (m-tile 0..3) x (n-half 0..1) ----
    const int m_off  = (warp & 3) << 4;
    const int n_base = (warp >> 2) * 256;
    const int row0   = m_off + g4;
    const int row1   = row0 + 8;

    uint32_t Af[2][4];
#pragma unroll
    for (int s = 0; s < 2; s++) {
        const int k0 = s * 16 + t4 * 2;
        Af[s][0] = *reinterpret_cast<const uint32_t*>(&g_A[row0 * 32 + k0]);
        Af[s][1] = *reinterpret_cast<const uint32_t*>(&g_A[row1 * 32 + k0]);
        Af[s][2] = *reinterpret_cast<const uint32_t*>(&g_A[row0 * 32 + k0 + 8]);
        Af[s][3] = *reinterpret_cast<const uint32_t*>(&g_A[row1 * 32 + k0 + 8]);
    }
    const float e0  = g_e[row0],  e1  = g_e[row1];
    const float rs0 = g_rs[row0], rs1 = g_rs[row1];

#pragma unroll 4
    for (int nc = 0; nc < 32; nc++) {
        const int nb   = n_base + nc * 8;
        const int nrow = nb + g4;
        const int lcol = nb + t4 * 2;
        const long gc  = col0 + lcol;

        float2 xv0, xv1;
        const bool pair_ok = (gc + 1 < (long)N);
        if (pair_ok) {
            xv0 = __ldg(reinterpret_cast<const float2*>(x + (size_t)row0 * N + gc));
            xv1 = __ldg(reinterpret_cast<const float2*>(x + (size_t)row1 * N + gc));
        }

        uint32_t b00 = W[t4 * WPITCH + nrow];
        uint32_t b01 = W[(t4 + 4) * WPITCH + nrow];
        uint32_t b10 = W[(t4 + 8) * WPITCH + nrow];
        uint32_t b11 = W[(t4 + 12) * WPITCH + nrow];

        float c0 = 0.f, c1 = 0.f, c2 = 0.f, c3 = 0.f;
        mma_m16n8k16(c0, c1, c2, c3, Af[0][0], Af[0][1], Af[0][2], Af[0][3], b00, b01);
        mma_m16n8k16(c0, c1, c2, c3, Af[1][0], Af[1][1], Af[1][2], Af[1][3], b10, b11);

        if (pair_ok) {
            const float2 m0 = msv[lcol], m1 = msv[lcol + 1];
            float2 o0, o1;
            o0.x = xv0.x + e0 + m0.y * (c0 - m0.x * rs0);
            o0.y = xv0.y + e0 + m1.y * (c1 - m1.x * rs0);
            o1.x = xv1.x + e1 + m0.y * (c2 - m0.x * rs1);
            o1.y = xv1.y + e1 + m1.y * (c3 - m1.x * rs1);
            __stcs(reinterpret_cast<float2*>(out + (size_t)row0 * N + gc), o0);
            __stcs(reinterpret_cast<float2*>(out + (size_t)row1 * N + gc), o1);
        } else if (gc < (long)N) {
            const float2 m0 = msv[lcol];
            const float xa = x[(size_t)row0 * N + gc];
            out[(size_t)row0 * N + gc] = xa + e0 + m0.y * (c0 - m0.x * rs0);
            const float xb = x[(size_t)row1 * N + gc];
            out[(size_t)row1 * N + gc] = xb + e1 + m0.y * (c2 - m0.x * rs1);
        }
    }
}

// ============================================================================
extern "C" void kernel_launch(void* const* d_in, const int* in_sizes, int n_in,
                              void* d_out, int out_size)
{
    const float* x     = (const float*)d_in[0];
    const float* gamma = (const float*)d_in[1];
    const float* beta  = (const float*)d_in[2];
    const float* cw    = (const float*)d_in[3];
    const float* cb    = (const float*)d_in[4];
    float* out = (float*)d_out;

    const int N = in_sizes[0] / 64;
    const int nchunks = (N + TILE - 1) / TILE;
    const int nb1 = nchunks < P1MAX ? nchunks : P1MAX;

    k_pass1<<<nb1, NTHR>>>(x, N, nchunks);
    k_reduce<<<(PART_STRIDE + 255) / 256, 256>>>(nb1);
    k_pass2<<<1, 64>>>(gamma, beta, cw, cb, (float)N);
    k_pass3<<<nchunks, NTHR>>>(x, out, N);
}

// round 7
// speedup vs baseline: 2.2315x; 2.2315x over previous
#include <cuda_runtime.h>
#include <cuda_bf16.h>
#include <stdint.h>

#define LN_EPS 1e-5f

namespace {
constexpr int TILE    = 256;   // columns per chunk
constexpr int NTHR    = 256;
constexpr int XPITCH  = 260;   // fp32 words per row (260 % 32 == 4 -> conflict-free frags)
constexpr int ZPITCH  = 132;   // u32 words per Z row (132 % 32 == 4)
constexpr int P1CTAS  = 296;   // persistent pass1 CTAs (2/SM)
constexpr int GRAM_E  = 1024;
constexpr int UE      = 48;
constexpr int PART_STRIDE = GRAM_E + UE;   // 1072
constexpr int MAXN    = 1 << 21;

constexpr int XS_BYTES = 64 * XPITCH * 4;            // 66560
constexpr int ZW_BYTES = 48 * ZPITCH * 4;            // 25344
constexpr int P1_MSV   = XS_BYTES + ZW_BYTES;        // 91904
constexpr int P1_SMEM  = P1_MSV + TILE * 8;          // 93952
constexpr int P3_MSV   = XS_BYTES;
constexpr int P3_SMEM  = XS_BYTES + TILE * 8;        // 68608
}

// ---- scratch (allocation-free: __device__ globals) ----
__device__ float g_part[P1CTAS * PART_STRIDE];
__device__ float g_gram[GRAM_E];
__device__ float g_u[UE];
__device__ __align__(16) __nv_bfloat16 g_A[64 * 32];
__device__ float g_e[64];
__device__ float g_rs[64];
__device__ __align__(16) float2 g_msv[MAXN];   // (mu, rv) per column

__device__ __forceinline__ void mma_m16n8k16(
    float& d0, float& d1, float& d2, float& d3,
    uint32_t a0, uint32_t a1, uint32_t a2, uint32_t a3,
    uint32_t b0, uint32_t b1)
{
    asm volatile(
        "mma.sync.aligned.m16n8k16.row.col.f32.bf16.bf16.f32 "
        "{%0,%1,%2,%3}, {%4,%5,%6,%7}, {%8,%9}, {%0,%1,%2,%3};\n"
        : "+f"(d0), "+f"(d1), "+f"(d2), "+f"(d3)
        : "r"(a0), "r"(a1), "r"(a2), "r"(a3), "r"(b0), "r"(b1));
}

__device__ __forceinline__ uint32_t pack_bf16(float lo, float hi) {
    __nv_bfloat162 b = __floats2bfloat162_rn(lo, hi);
    return *reinterpret_cast<uint32_t*>(&b);
}
__device__ __forceinline__ float bf_lo(uint32_t u) {
    __nv_bfloat162 b = *reinterpret_cast<__nv_bfloat162*>(&u);
    return __bfloat162float(b.x);
}
__device__ __forceinline__ float bf_hi(uint32_t u) {
    __nv_bfloat162 b = *reinterpret_cast<__nv_bfloat162*>(&u);
    return __bfloat162float(b.y);
}
__device__ __forceinline__ uint32_t smem_u32(const void* p) {
    return (uint32_t)__cvta_generic_to_shared(p);
}

// issue one full tile (64 rows x 256 cols fp32) as 16 cp.async.16B per thread
__device__ __forceinline__ void cp_tile(const float* __restrict__ x, long col0,
                                        int N, uint32_t xs_base, int tid)
{
#pragma unroll
    for (int i = 0; i < 16; i++) {
        const int chunk = tid + 256 * i;
        const int row = chunk >> 6;      // 64 chunks per row
        const int seg = chunk & 63;
        const float* src = x + (size_t)row * N + col0 + seg * 4;
        const uint32_t dst = xs_base + (uint32_t)(row * XPITCH + seg * 4) * 4u;
        asm volatile("cp.async.cg.shared.global [%0], [%1], 16;\n"
                     :: "r"(dst), "l"(src));
    }
    asm volatile("cp.async.commit_group;\n");
}
__device__ __forceinline__ void cp_wait_all() {
    asm volatile("cp.async.wait_group 0;\n" ::: "memory");
}

// ============================================================================
// Pass 1 (persistent): cp.async tile -> stats (g_msv) -> bf16 Z -> prefetch
// next tile -> row sums u + 32x32 Gram (rows [0,32) x [16,48))
// ============================================================================
__global__ __launch_bounds__(NTHR) void k_pass1(const float* __restrict__ x,
                                                int N, int nchunks)
{
    extern __shared__ __align__(16) char smem[];
    float*    Xs    = reinterpret_cast<float*>(smem);
    uint32_t* Zw    = reinterpret_cast<uint32_t*>(smem + XS_BYTES);
    float2*   msv_s = reinterpret_cast<float2*>(smem + P1_MSV);
    const uint32_t xs_base = smem_u32(Xs);

    const int tid  = threadIdx.x;
    const int warp = tid >> 5;
    const int lane = tid & 31;
    const int g4   = lane >> 2;
    const int t4   = lane & 3;
    const int m_off = (warp >> 2) << 4;   // 0/16
    const int n_off = (warp & 3) << 3;    // 0,8,16,24
    const int wc   = tid & 127;           // word-col for normalize
    const int rb0  = (tid >> 7) * 24;     // row base for normalize

    const bool fastN = ((N & 3) == 0);

    float d0 = 0.f, d1 = 0.f, d2 = 0.f, d3 = 0.f;
    float ured[6] = {0.f, 0.f, 0.f, 0.f, 0.f, 0.f};

    // prologue prefetch
    {
        const long c0 = (long)blockIdx.x * TILE;
        if (blockIdx.x < nchunks && fastN && c0 + TILE <= (long)N)
            cp_tile(x, c0, N, xs_base, tid);
    }

    for (int chunk = blockIdx.x; chunk < nchunks; chunk += gridDim.x) {
        const long col0 = (long)chunk * TILE;
        const bool fast = fastN && (col0 + TILE <= (long)N);

        if (fast) {
            cp_wait_all();
        } else {
            const long c = col0 + tid;
#pragma unroll 1
            for (int r = 0; r < 64; r++)
                Xs[r * XPITCH + tid] = (c < (long)N) ? __ldg(x + (size_t)r * N + c) : 0.f;
        }
        __syncthreads();

        // ---- stats: thread owns column tid ----
        {
            float s1 = 0.f, s2 = 0.f;
#pragma unroll
            for (int r = 0; r < 64; r++) {
                const float v = Xs[r * XPITCH + tid];
                s1 += v;
                s2 = fmaf(v, v, s2);
            }
            const float mu = s1 * (1.f / 64.f);
            const float rv = rsqrtf(s2 * (1.f / 64.f) - mu * mu + LN_EPS);
            msv_s[tid] = make_float2(mu, rv);
            if (col0 + tid < (long)N) g_msv[col0 + tid] = make_float2(mu, rv);
        }
        __syncthreads();

        // ---- normalize rows 0..47 into bf16 Z ----
        {
            const float2 mv0 = msv_s[2 * wc];
            const float2 mv1 = msv_s[2 * wc + 1];
#pragma unroll
            for (int j = 0; j < 24; j++) {
                const int r = rb0 + j;
                const float2 v = *reinterpret_cast<const float2*>(&Xs[r * XPITCH + 2 * wc]);
                Zw[r * ZPITCH + wc] =
                    pack_bf16((v.x - mv0.x) * mv0.y, (v.y - mv1.x) * mv1.y);
            }
        }
        __syncthreads();   // Zw ready; Xs free

        // ---- prefetch next tile while computing Gram ----
        {
            const int nxt = chunk + gridDim.x;
            const long nc0 = (long)nxt * TILE;
            if (nxt < nchunks && fastN && nc0 + TILE <= (long)N)
                cp_tile(x, nc0, N, xs_base, tid);
        }

        // ---- row sums u (8 warps x 6 rows) ----
#pragma unroll
        for (int rr = 0; rr < 6; rr++) {
            const int row = warp + rr * 8;
            float s = 0.f;
#pragma unroll
            for (int i = 0; i < 4; i++) {
                const uint32_t w = Zw[row * ZPITCH + lane + 32 * i];
                s += bf_lo(w) + bf_hi(w);
            }
#pragma unroll
            for (int off = 16; off; off >>= 1)
                s += __shfl_xor_sync(0xffffffffu, s, off);
            ured[rr] += s;
        }

        // ---- Gram: D[32x32] += Z[0:32] * Z[16:48]^T over 256 columns ----
        const int ra = m_off + g4;
        const int rbq = 16 + n_off + g4;
#pragma unroll 4
        for (int kk = 0; kk < 16; kk++) {
            const int kw = kk * 8 + t4;
            uint32_t a0 = Zw[ra * ZPITCH + kw];
            uint32_t a1 = Zw[(ra + 8) * ZPITCH + kw];
            uint32_t a2 = Zw[ra * ZPITCH + kw + 4];
            uint32_t a3 = Zw[(ra + 8) * ZPITCH + kw + 4];
            uint32_t b0 = Zw[rbq * ZPITCH + kw];
            uint32_t b1 = Zw[rbq * ZPITCH + kw + 4];
            mma_m16n8k16(d0, d1, d2, d3, a0, a1, a2, a3, b0, b1);
        }
        __syncthreads();   // Zw free before next normalize
    }

    // ---- deterministic per-CTA partials ----
    float* pp = g_part + (size_t)blockIdx.x * PART_STRIDE;
    const int row0 = m_off + g4;
    const int colp = n_off + t4 * 2;
    pp[row0 * 32 + colp]           = d0;
    pp[row0 * 32 + colp + 1]       = d1;
    pp[(row0 + 8) * 32 + colp]     = d2;
    pp[(row0 + 8) * 32 + colp + 1] = d3;
    if (lane == 0) {
#pragma unroll
        for (int rr = 0; rr < 6; rr++)
            pp[GRAM_E + warp + rr * 8] = ured[rr];
    }
}

// ============================================================================
// Reduce partials (deterministic)
// ============================================================================
__global__ void k_reduce(int nb)
{
    const int e = blockIdx.x * blockDim.x + threadIdx.x;
    if (e >= PART_STRIDE) return;
    float s = 0.f;
    for (int c = 0; c < nb; c++) s += g_part[(size_t)c * PART_STRIDE + e];
    if (e < GRAM_E) g_gram[e] = s;
    else            g_u[e - GRAM_E] = s;
}

// ============================================================================
// Pass 2 (1 block, 64 threads): logits -> softmax -> A[64x32], e[64], rs[64]
// ============================================================================
__global__ void k_pass2(const float* __restrict__ gamma,
                        const float* __restrict__ beta,
                        const float* __restrict__ cw,
                        const float* __restrict__ cb,
                        float Nf)
{
    __shared__ float Gs[GRAM_E];
    __shared__ float us[UE];
    __shared__ float gs[64], bs[64];

    const int c = threadIdx.x;
    for (int i = c; i < GRAM_E; i += 64) Gs[i] = g_gram[i];
    if (c < UE) us[c] = g_u[c];
    gs[c] = gamma[c];
    bs[c] = beta[c];
    __syncthreads();

    const float wq = cw[c], bq = cb[c];
    const int   iq = c / 3;
    const float gi = gs[iq], bi = bs[iq], ui = us[iq];
    const float ti = gi * ui + Nf * bi;

    float L[64];
    float mx = -1e30f;
#pragma unroll 1
    for (int b2 = 0; b2 < 64; b2++) {
        const int   ik = (64 + b2) / 3;
        const float wk = cw[64 + b2], bk = cb[64 + b2];
        const float gj = gs[ik], bj = bs[ik], uj = us[ik];
        const float tj = gj * uj + Nf * bj;
        const float Gz = Gs[iq * 32 + (ik - 16)];
        const float S  = gi * gj * Gz + gi * bj * ui + bi * gj * uj + Nf * bi * bj;
        const float l  = 0.125f * (wq * wk * S + wq * bk * ti + bq * wk * tj + Nf * bq * bk);
        L[b2] = l;
        mx = fmaxf(mx, l);
    }
    float se = 0.f;
#pragma unroll 1
    for (int b2 = 0; b2 < 64; b2++) {
        const float ev = expf(L[b2] - mx);
        L[b2] = ev;
        se += ev;
    }
    const float inv = 1.f / se;

    float eacc = 0.f;
#pragma unroll 1
    for (int b2 = 0; b2 < 64; b2++) {
        L[b2] *= inv;
        eacc += L[b2] * cb[128 + b2];
    }

    float rssum = 0.f;
#pragma unroll 1
    for (int j = 32; j < 64; j++) {
        float P = 0.f;
        const int b0 = 3 * j - 128;
#pragma unroll
        for (int d = 0; d < 3; d++) {
            const int bb = b0 + d;
            if (bb >= 0 && bb < 64) P += L[bb] * cw[128 + bb];
        }
        const float Av = P * gs[j];
        const __nv_bfloat16 ab = __float2bfloat16(Av);
        g_A[c * 32 + (j - 32)] = ab;
        rssum += __bfloat162float(ab);
        eacc  += P * bs[j];
    }
    g_e[c]  = eacc;
    g_rs[c] = rssum;
}

// ============================================================================
// Pass 3: cp.async full 64x256 fp32 tile -> (from smem) bf16 B frags + MMA +
// residual + epilogue; only stores touch DRAM in the hot loop.
// ============================================================================
__global__ __launch_bounds__(NTHR) void k_pass3(const float* __restrict__ x,
                                                float* __restrict__ out, int N)
{
    extern __shared__ __align__(16) char smem[];
    float*  Xs    = reinterpret_cast<float*>(smem);
    float2* msv_s = reinterpret_cast<float2*>(smem + P3_MSV);
    const uint32_t xs_base = smem_u32(Xs);

    const int tid  = threadIdx.x;
    const int warp = tid >> 5;
    const int lane = tid & 31;
    const int g4   = lane >> 2;
    const int t4   = lane & 3;

    const long col0 = (long)blockIdx.x * TILE;
    const bool fast = ((N & 3) == 0) && (col0 + TILE <= (long)N);

    if (fast) {
        cp_tile(x, col0, N, xs_base, tid);
        msv_s[tid] = g_msv[col0 + tid];
        cp_wait_all();
    } else {
        const long c = col0 + tid;
        msv_s[tid] = (c < (long)N) ? g_msv[c] : make_float2(0.f, 1.f);
#pragma unroll 1
        for (int r = 0; r < 64; r++)
            Xs[r * XPITCH + tid] = (c < (long)N) ? __ldg(x + (size_t)r * N + c) : 0.f;
    }
    __syncthreads();

    // ---- warp = (m-tile 0..3) x (n-half 0..1); 16 n8-iters each ----
    const int m_off  = (warp & 3) << 4;
    const int n_base = (warp >> 2) * 128;
    const int row0   = m_off + g4;
    const int row1   = row0 + 8;

    uint32_t Af[2][4];
#pragma unroll
    for (int s = 0; s < 2; s++) {
        const int k0 = s * 16 + t4 * 2;
        Af[s][0] = *reinterpret_cast<const uint32_t*>(&g_A[row0 * 32 + k0]);
        Af[s][1] = *reinterpret_cast<const uint32_t*>(&g_A[row1 * 32 + k0]);
        Af[s][2] = *reinterpret_cast<const uint32_t*>(&g_A[row0 * 32 + k0 + 8]);
        Af[s][3] = *reinterpret_cast<const uint32_t*>(&g_A[row1 * 32 + k0 + 8]);
    }
    const float e0  = g_e[row0],  e1  = g_e[row1];
    const float rs0 = g_rs[row0], rs1 = g_rs[row1];

#pragma unroll 4
    for (int nc = 0; nc < 16; nc++) {
        const int nb   = n_base + nc * 8;
        const int nrow = nb + g4;
        const int lcol = nb + 2 * t4;
        const long gc  = col0 + lcol;

        // B fragments built from fp32 smem rows 32..63 (pitch%32==4 -> no conflicts)
        const int kr = 32 + 2 * t4;
        uint32_t b00 = pack_bf16(Xs[kr * XPITCH + nrow],        Xs[(kr + 1) * XPITCH + nrow]);
        uint32_t b01 = pack_bf16(Xs[(kr + 8) * XPITCH + nrow],  Xs[(kr + 9) * XPITCH + nrow]);
        uint32_t b10 = pack_bf16(Xs[(kr + 16) * XPITCH + nrow], Xs[(kr + 17) * XPITCH + nrow]);
        uint32_t b11 = pack_bf16(Xs[(kr + 24) * XPITCH + nrow], Xs[(kr + 25) * XPITCH + nrow]);

        float c0 = 0.f, c1 = 0.f, c2 = 0.f, c3 = 0.f;
        mma_m16n8k16(c0, c1, c2, c3, Af[0][0], Af[0][1], Af[0][2], Af[0][3], b00, b01);
        mma_m16n8k16(c0, c1, c2, c3, Af[1][0], Af[1][1], Af[1][2], Af[1][3], b10, b11);

        // residual + stats from smem
        const float2 xv0 = *reinterpret_cast<const float2*>(&Xs[row0 * XPITCH + lcol]);
        const float2 xv1 = *reinterpret_cast<const float2*>(&Xs[row1 * XPITCH + lcol]);
        const float2 m0 = msv_s[lcol], m1 = msv_s[lcol + 1];

        float2 o0, o1;
        o0.x = xv0.x + e0 + m0.y * (c0 - m0.x * rs0);
        o0.y = xv0.y + e0 + m1.y * (c1 - m1.x * rs0);
        o1.x = xv1.x + e1 + m0.y * (c2 - m0.x * rs1);
        o1.y = xv1.y + e1 + m1.y * (c3 - m1.x * rs1);

        if (gc + 1 < (long)N) {
            __stcs(reinterpret_cast<float2*>(out + (size_t)row0 * N + gc), o0);
            __stcs(reinterpret_cast<float2*>(out + (size_t)row1 * N + gc), o1);
        } else if (gc < (long)N) {
            out[(size_t)row0 * N + gc] = o0.x;
            out[(size_t)row1 * N + gc] = o1.x;
        }
    }
}

// ============================================================================
extern "C" void kernel_launch(void* const* d_in, const int* in_sizes, int n_in,
                              void* d_out, int out_size)
{
    const float* x     = (const float*)d_in[0];
    const float* gamma = (const float*)d_in[1];
    const float* beta  = (const float*)d_in[2];
    const float* cw    = (const float*)d_in[3];
    const float* cb    = (const float*)d_in[4];
    float* out = (float*)d_out;

    const int N = in_sizes[0] / 64;
    const int nchunks = (N + TILE - 1) / TILE;
    const int nb1 = nchunks < P1CTAS ? nchunks : P1CTAS;

    cudaFuncSetAttribute(k_pass1, cudaFuncAttributeMaxDynamicSharedMemorySize, P1_SMEM);
    cudaFuncSetAttribute(k_pass3, cudaFuncAttributeMaxDynamicSharedMemorySize, P3_SMEM);

    k_pass1<<<nb1, NTHR, P1_SMEM>>>(x, N, nchunks);
    k_reduce<<<(PART_STRIDE + 255) / 256, 256>>>(nb1);
    k_pass2<<<1, 64>>>(gamma, beta, cw, cb, (float)N);
    k_pass3<<<nchunks, NTHR, P3_SMEM>>>(x, out, N);
}

// round 8
// speedup vs baseline: 2.2362x; 1.0021x over previous
#include <cuda_runtime.h>
#include <cuda_bf16.h>
#include <stdint.h>

#define LN_EPS 1e-5f

namespace {
constexpr int TILE    = 256;   // pass1 columns per chunk
constexpr int NTHR    = 256;
constexpr int XPITCH  = 260;   // pass1 fp32 words per row
constexpr int ZPITCH  = 132;   // pass1 Z words per row
constexpr int P1CTAS  = 296;
constexpr int GRAM_E  = 1024;
constexpr int UE      = 48;
constexpr int PART_STRIDE = GRAM_E + UE;
constexpr int MAXN    = 1 << 21;

constexpr int XS_BYTES = 64 * XPITCH * 4;            // 66560
constexpr int ZW_BYTES = 48 * ZPITCH * 4;            // 25344
constexpr int P1_MSV   = XS_BYTES + ZW_BYTES;
constexpr int P1_SMEM  = P1_MSV + TILE * 8;          // 93952

// pass3 pipelined chunks
constexpr int CH      = 128;   // columns per pass3 chunk
constexpr int XP3     = 132;   // words per row per buffer (132 % 32 == 4)
constexpr int BUF_B   = 64 * XP3 * 4;                // 33792
constexpr int MSV_B   = CH * 8;                      // 1024
constexpr int P3_SMEM = 2 * BUF_B + 2 * MSV_B;       // 69632
constexpr int P3CTAS  = 444;   // 148 SMs * 3
}

// ---- scratch (allocation-free: __device__ globals) ----
__device__ float g_part[P1CTAS * PART_STRIDE];
__device__ float g_gram[GRAM_E];
__device__ float g_u[UE];
__device__ __align__(16) __nv_bfloat16 g_A[64 * 32];
__device__ float g_e[64];
__device__ float g_rs[64];
__device__ __align__(16) float2 g_msv[MAXN];

__device__ __forceinline__ void mma_m16n8k16(
    float& d0, float& d1, float& d2, float& d3,
    uint32_t a0, uint32_t a1, uint32_t a2, uint32_t a3,
    uint32_t b0, uint32_t b1)
{
    asm volatile(
        "mma.sync.aligned.m16n8k16.row.col.f32.bf16.bf16.f32 "
        "{%0,%1,%2,%3}, {%4,%5,%6,%7}, {%8,%9}, {%0,%1,%2,%3};\n"
        : "+f"(d0), "+f"(d1), "+f"(d2), "+f"(d3)
        : "r"(a0), "r"(a1), "r"(a2), "r"(a3), "r"(b0), "r"(b1));
}

__device__ __forceinline__ uint32_t pack_bf16(float lo, float hi) {
    __nv_bfloat162 b = __floats2bfloat162_rn(lo, hi);
    return *reinterpret_cast<uint32_t*>(&b);
}
__device__ __forceinline__ float bf_lo(uint32_t u) {
    __nv_bfloat162 b = *reinterpret_cast<__nv_bfloat162*>(&u);
    return __bfloat162float(b.x);
}
__device__ __forceinline__ float bf_hi(uint32_t u) {
    __nv_bfloat162 b = *reinterpret_cast<__nv_bfloat162*>(&u);
    return __bfloat162float(b.y);
}
__device__ __forceinline__ uint32_t smem_u32(const void* p) {
    return (uint32_t)__cvta_generic_to_shared(p);
}
__device__ __forceinline__ void cp16(uint32_t dst, const void* src) {
    asm volatile("cp.async.cg.shared.global [%0], [%1], 16;\n" :: "r"(dst), "l"(src));
}
__device__ __forceinline__ void cp_commit() {
    asm volatile("cp.async.commit_group;\n");
}
__device__ __forceinline__ void cp_wait0() {
    asm volatile("cp.async.wait_group 0;\n" ::: "memory");
}
__device__ __forceinline__ void cp_wait1() {
    asm volatile("cp.async.wait_group 1;\n" ::: "memory");
}

// ============================================================================
// Pass 1 (persistent): cp.async tile -> stats (g_msv) -> bf16 Z -> prefetch
// next tile -> row sums u + 32x32 Gram (rows [0,32) x [16,48))
// ============================================================================
__global__ __launch_bounds__(NTHR) void k_pass1(const float* __restrict__ x,
                                                int N, int nchunks)
{
    extern __shared__ __align__(16) char smem[];
    float*    Xs    = reinterpret_cast<float*>(smem);
    uint32_t* Zw    = reinterpret_cast<uint32_t*>(smem + XS_BYTES);
    float2*   msv_s = reinterpret_cast<float2*>(smem + P1_MSV);
    const uint32_t xs_base = smem_u32(Xs);

    const int tid  = threadIdx.x;
    const int warp = tid >> 5;
    const int lane = tid & 31;
    const int g4   = lane >> 2;
    const int t4   = lane & 3;
    const int m_off = (warp >> 2) << 4;
    const int n_off = (warp & 3) << 3;
    const int wc   = tid & 127;
    const int rb0  = (tid >> 7) * 24;
    const int c2   = tid >> 1;       // column pair index (fast stats)
    const int rh   = tid & 1;        // row half

    const bool fastN = ((N & 3) == 0);

    float d0 = 0.f, d1 = 0.f, d2 = 0.f, d3 = 0.f;
    float ured[6] = {0.f, 0.f, 0.f, 0.f, 0.f, 0.f};

    // prologue prefetch
    {
        const long c0 = (long)blockIdx.x * TILE;
        if (blockIdx.x < nchunks && fastN && c0 + TILE <= (long)N) {
#pragma unroll
            for (int i = 0; i < 16; i++) {
                const int ck = tid + 256 * i;
                const int row = ck >> 6, seg = ck & 63;
                cp16(xs_base + (uint32_t)(row * XPITCH + seg * 4) * 4u,
                     x + (size_t)row * N + c0 + seg * 4);
            }
        }
        cp_commit();
    }

    for (int chunk = blockIdx.x; chunk < nchunks; chunk += gridDim.x) {
        const long col0 = (long)chunk * TILE;
        const bool fast = fastN && (col0 + TILE <= (long)N);

        cp_wait0();
        if (!fast) {
            const long c = col0 + tid;
#pragma unroll 1
            for (int r = 0; r < 64; r++)
                Xs[r * XPITCH + tid] = (c < (long)N) ? __ldg(x + (size_t)r * N + c) : 0.f;
        }
        __syncthreads();

        // ---- stats: float2 loads, partner = lane^1 ----
        if (fast) {
            float s1x = 0.f, s1y = 0.f, s2x = 0.f, s2y = 0.f;
            const float* px = &Xs[(rh * 32) * XPITCH + 2 * c2];
#pragma unroll
            for (int r = 0; r < 32; r++) {
                const float2 v = *reinterpret_cast<const float2*>(&px[r * XPITCH]);
                s1x += v.x; s1y += v.y;
                s2x = fmaf(v.x, v.x, s2x);
                s2y = fmaf(v.y, v.y, s2y);
            }
            s1x += __shfl_xor_sync(0xffffffffu, s1x, 1);
            s1y += __shfl_xor_sync(0xffffffffu, s1y, 1);
            s2x += __shfl_xor_sync(0xffffffffu, s2x, 1);
            s2y += __shfl_xor_sync(0xffffffffu, s2y, 1);
            if (!rh) {
                const float mux = s1x * (1.f / 64.f), muy = s1y * (1.f / 64.f);
                const float rvx = rsqrtf(s2x * (1.f / 64.f) - mux * mux + LN_EPS);
                const float rvy = rsqrtf(s2y * (1.f / 64.f) - muy * muy + LN_EPS);
                msv_s[2 * c2]     = make_float2(mux, rvx);
                msv_s[2 * c2 + 1] = make_float2(muy, rvy);
                *reinterpret_cast<float4*>(&g_msv[col0 + 2 * c2]) =
                    make_float4(mux, rvx, muy, rvy);
            }
        } else {
            float s1 = 0.f, s2 = 0.f;
#pragma unroll 1
            for (int r = 0; r < 64; r++) {
                const float v = Xs[r * XPITCH + tid];
                s1 += v; s2 = fmaf(v, v, s2);
            }
            const float mu = s1 * (1.f / 64.f);
            const float rv = rsqrtf(s2 * (1.f / 64.f) - mu * mu + LN_EPS);
            msv_s[tid] = make_float2(mu, rv);
            if (col0 + tid < (long)N) g_msv[col0 + tid] = make_float2(mu, rv);
        }
        __syncthreads();

        // ---- normalize rows 0..47 into bf16 Z ----
        {
            const float2 mv0 = msv_s[2 * wc];
            const float2 mv1 = msv_s[2 * wc + 1];
#pragma unroll
            for (int j = 0; j < 24; j++) {
                const int r = rb0 + j;
                const float2 v = *reinterpret_cast<const float2*>(&Xs[r * XPITCH + 2 * wc]);
                Zw[r * ZPITCH + wc] =
                    pack_bf16((v.x - mv0.x) * mv0.y, (v.y - mv1.x) * mv1.y);
            }
        }
        __syncthreads();   // Zw ready; Xs free

        // ---- prefetch next tile while computing Gram ----
        {
            const int nxt = chunk + gridDim.x;
            const long nc0 = (long)nxt * TILE;
            if (nxt < nchunks && fastN && nc0 + TILE <= (long)N) {
#pragma unroll
                for (int i = 0; i < 16; i++) {
                    const int ck = tid + 256 * i;
                    const int row = ck >> 6, seg = ck & 63;
                    cp16(xs_base + (uint32_t)(row * XPITCH + seg * 4) * 4u,
                         x + (size_t)row * N + nc0 + seg * 4);
                }
            }
            cp_commit();
        }

        // ---- row sums u ----
#pragma unroll
        for (int rr = 0; rr < 6; rr++) {
            const int row = warp + rr * 8;
            float s = 0.f;
#pragma unroll
            for (int i = 0; i < 4; i++) {
                const uint32_t w = Zw[row * ZPITCH + lane + 32 * i];
                s += bf_lo(w) + bf_hi(w);
            }
#pragma unroll
            for (int off = 16; off; off >>= 1)
                s += __shfl_xor_sync(0xffffffffu, s, off);
            ured[rr] += s;
        }

        // ---- Gram over 256 columns ----
        const int ra = m_off + g4;
        const int rbq = 16 + n_off + g4;
#pragma unroll 4
        for (int kk = 0; kk < 16; kk++) {
            const int kw = kk * 8 + t4;
            uint32_t a0 = Zw[ra * ZPITCH + kw];
            uint32_t a1 = Zw[(ra + 8) * ZPITCH + kw];
            uint32_t a2 = Zw[ra * ZPITCH + kw + 4];
            uint32_t a3 = Zw[(ra + 8) * ZPITCH + kw + 4];
            uint32_t b0 = Zw[rbq * ZPITCH + kw];
            uint32_t b1 = Zw[rbq * ZPITCH + kw + 4];
            mma_m16n8k16(d0, d1, d2, d3, a0, a1, a2, a3, b0, b1);
        }
        __syncthreads();
    }

    float* pp = g_part + (size_t)blockIdx.x * PART_STRIDE;
    const int row0 = m_off + g4;
    const int colp = n_off + t4 * 2;
    pp[row0 * 32 + colp]           = d0;
    pp[row0 * 32 + colp + 1]       = d1;
    pp[(row0 + 8) * 32 + colp]     = d2;
    pp[(row0 + 8) * 32 + colp + 1] = d3;
    if (lane == 0) {
#pragma unroll
        for (int rr = 0; rr < 6; rr++)
            pp[GRAM_E + warp + rr * 8] = ured[rr];
    }
}

// ============================================================================
__global__ void k_reduce(int nb)
{
    const int e = blockIdx.x * blockDim.x + threadIdx.x;
    if (e >= PART_STRIDE) return;
    float s = 0.f;
    for (int c = 0; c < nb; c++) s += g_part[(size_t)c * PART_STRIDE + e];
    if (e < GRAM_E) g_gram[e] = s;
    else            g_u[e - GRAM_E] = s;
}

// ============================================================================
__global__ void k_pass2(const float* __restrict__ gamma,
                        const float* __restrict__ beta,
                        const float* __restrict__ cw,
                        const float* __restrict__ cb,
                        float Nf)
{
    __shared__ float Gs[GRAM_E];
    __shared__ float us[UE];
    __shared__ float gs[64], bs[64];

    const int c = threadIdx.x;
    for (int i = c; i < GRAM_E; i += 64) Gs[i] = g_gram[i];
    if (c < UE) us[c] = g_u[c];
    gs[c] = gamma[c];
    bs[c] = beta[c];
    __syncthreads();

    const float wq = cw[c], bq = cb[c];
    const int   iq = c / 3;
    const float gi = gs[iq], bi = bs[iq], ui = us[iq];
    const float ti = gi * ui + Nf * bi;

    float L[64];
    float mx = -1e30f;
#pragma unroll 1
    for (int b2 = 0; b2 < 64; b2++) {
        const int   ik = (64 + b2) / 3;
        const float wk = cw[64 + b2], bk = cb[64 + b2];
        const float gj = gs[ik], bj = bs[ik], uj = us[ik];
        const float tj = gj * uj + Nf * bj;
        const float Gz = Gs[iq * 32 + (ik - 16)];
        const float S  = gi * gj * Gz + gi * bj * ui + bi * gj * uj + Nf * bi * bj;
        const float l  = 0.125f * (wq * wk * S + wq * bk * ti + bq * wk * tj + Nf * bq * bk);
        L[b2] = l;
        mx = fmaxf(mx, l);
    }
    float se = 0.f;
#pragma unroll 1
    for (int b2 = 0; b2 < 64; b2++) {
        const float ev = expf(L[b2] - mx);
        L[b2] = ev;
        se += ev;
    }
    const float inv = 1.f / se;

    float eacc = 0.f;
#pragma unroll 1
    for (int b2 = 0; b2 < 64; b2++) {
        L[b2] *= inv;
        eacc += L[b2] * cb[128 + b2];
    }

    float rssum = 0.f;
#pragma unroll 1
    for (int j = 32; j < 64; j++) {
        float P = 0.f;
        const int b0 = 3 * j - 128;
#pragma unroll
        for (int d = 0; d < 3; d++) {
            const int bb = b0 + d;
            if (bb >= 0 && bb < 64) P += L[bb] * cw[128 + bb];
        }
        const float Av = P * gs[j];
        const __nv_bfloat16 ab = __float2bfloat16(Av);
        g_A[c * 32 + (j - 32)] = ab;
        rssum += __bfloat162float(ab);
        eacc  += P * bs[j];
    }
    g_e[c]  = eacc;
    g_rs[c] = rssum;
}

// ============================================================================
// Pass 3 (persistent, pipelined): 128-col chunks, double-buffered cp.async.
// While computing chunk i, chunk i+1 streams in. out = x + e + rv*(A@x - mu*rs)
// ============================================================================
__global__ __launch_bounds__(NTHR) void k_pass3(const float* __restrict__ x,
                                                float* __restrict__ out,
                                                int N, int nchunks)
{
    extern __shared__ __align__(16) char smem[];
    const uint32_t base0 = smem_u32(smem);

    const int tid  = threadIdx.x;
    const int warp = tid >> 5;
    const int lane = tid & 31;
    const int g4   = lane >> 2;
    const int t4   = lane & 3;
    const bool fastN = ((N & 3) == 0);

    // per-warp constants
    const int m_off  = (warp & 3) << 4;
    const int n_base = (warp >> 2) * 64;
    const int row0   = m_off + g4;
    const int row1   = row0 + 8;

    uint32_t Af[2][4];
#pragma unroll
    for (int s = 0; s < 2; s++) {
        const int k0 = s * 16 + t4 * 2;
        Af[s][0] = *reinterpret_cast<const uint32_t*>(&g_A[row0 * 32 + k0]);
        Af[s][1] = *reinterpret_cast<const uint32_t*>(&g_A[row1 * 32 + k0]);
        Af[s][2] = *reinterpret_cast<const uint32_t*>(&g_A[row0 * 32 + k0 + 8]);
        Af[s][3] = *reinterpret_cast<const uint32_t*>(&g_A[row1 * 32 + k0 + 8]);
    }
    const float e0  = g_e[row0],  e1  = g_e[row1];
    const float rs0 = g_rs[row0], rs1 = g_rs[row1];

    // prefetch helper (lambda-free, inline twice via macro)
#define P3_PREFETCH(IDX, BUFSEL)                                               \
    do {                                                                       \
        const int _i = (IDX);                                                  \
        if (_i < nchunks) {                                                    \
            const long _c0 = (long)_i * CH;                                    \
            if (fastN && _c0 + CH <= (long)N) {                                \
                const uint32_t _xb = base0 + (BUFSEL) * BUF_B;                 \
                _Pragma("unroll")                                              \
                for (int _k = 0; _k < 8; _k++) {                               \
                    const int _ck = tid + 256 * _k;                            \
                    const int _row = _ck >> 5, _seg = _ck & 31;                \
                    cp16(_xb + (uint32_t)(_row * XP3 + _seg * 4) * 4u,         \
                         x + (size_t)_row * N + _c0 + _seg * 4);               \
                }                                                              \
                if (tid < 64)                                                  \
                    cp16(base0 + 2 * BUF_B + (BUFSEL) * MSV_B + tid * 16,      \
                         reinterpret_cast<const char*>(&g_msv[_c0]) + tid * 16);\
            }                                                                  \
        }                                                                      \
        cp_commit();                                                           \
    } while (0)

    int idx = blockIdx.x;
    P3_PREFETCH(idx, 0);
    P3_PREFETCH(idx + gridDim.x, 1);

    int cur = 0;
    for (; idx < nchunks; idx += gridDim.x, cur ^= 1) {
        const long col0 = (long)idx * CH;
        const bool fast = fastN && (col0 + CH <= (long)N);

        cp_wait1();   // oldest group (buf[cur]) complete
        float*  Xs    = reinterpret_cast<float*>(smem + cur * BUF_B);
        float2* msv_s = reinterpret_cast<float2*>(smem + 2 * BUF_B + cur * MSV_B);

        if (!fast) {
            // scalar fill (tail / odd-N chunks only)
#pragma unroll 1
            for (int i = tid; i < 64 * CH; i += NTHR) {
                const int r = i >> 7, cc = i & 127;
                const long c = col0 + cc;
                Xs[r * XP3 + cc] = (c < (long)N) ? __ldg(x + (size_t)r * N + c) : 0.f;
            }
            if (tid < CH) {
                const long c = col0 + tid;
                msv_s[tid] = (c < (long)N) ? g_msv[c] : make_float2(0.f, 1.f);
            }
        }
        __syncthreads();

        // ---- compute 64 x 128 chunk: 8 n8-iters per warp ----
#pragma unroll
        for (int nc = 0; nc < 8; nc++) {
            const int nb   = n_base + nc * 8;
            const int nrow = nb + g4;
            const int lcol = nb + 2 * t4;
            const long gc  = col0 + lcol;

            const int kr = 32 + 2 * t4;
            uint32_t b00 = pack_bf16(Xs[kr * XP3 + nrow],        Xs[(kr + 1) * XP3 + nrow]);
            uint32_t b01 = pack_bf16(Xs[(kr + 8) * XP3 + nrow],  Xs[(kr + 9) * XP3 + nrow]);
            uint32_t b10 = pack_bf16(Xs[(kr + 16) * XP3 + nrow], Xs[(kr + 17) * XP3 + nrow]);
            uint32_t b11 = pack_bf16(Xs[(kr + 24) * XP3 + nrow], Xs[(kr + 25) * XP3 + nrow]);

            float c0 = 0.f, c1 = 0.f, c2 = 0.f, c3 = 0.f;
            mma_m16n8k16(c0, c1, c2, c3, Af[0][0], Af[0][1], Af[0][2], Af[0][3], b00, b01);
            mma_m16n8k16(c0, c1, c2, c3, Af[1][0], Af[1][1], Af[1][2], Af[1][3], b10, b11);

            const float2 xv0 = *reinterpret_cast<const float2*>(&Xs[row0 * XP3 + lcol]);
            const float2 xv1 = *reinterpret_cast<const float2*>(&Xs[row1 * XP3 + lcol]);
            const float2 m0 = msv_s[lcol], m1 = msv_s[lcol + 1];

            float2 o0, o1;
            o0.x = xv0.x + e0 + m0.y * (c0 - m0.x * rs0);
            o0.y = xv0.y + e0 + m1.y * (c1 - m1.x * rs0);
            o1.x = xv1.x + e1 + m0.y * (c2 - m0.x * rs1);
            o1.y = xv1.y + e1 + m1.y * (c3 - m1.x * rs1);

            if (gc + 1 < (long)N) {
                __stcs(reinterpret_cast<float2*>(out + (size_t)row0 * N + gc), o0);
                __stcs(reinterpret_cast<float2*>(out + (size_t)row1 * N + gc), o1);
            } else if (gc < (long)N) {
                out[(size_t)row0 * N + gc] = o0.x;
                out[(size_t)row1 * N + gc] = o1.x;
            }
        }
        __syncthreads();   // all reads of buf[cur] done before refill

        P3_PREFETCH(idx + 2 * gridDim.x, cur);
    }
#undef P3_PREFETCH
}

// ============================================================================
extern "C" void kernel_launch(void* const* d_in, const int* in_sizes, int n_in,
                              void* d_out, int out_size)
{
    const float* x     = (const float*)d_in[0];
    const float* gamma = (const float*)d_in[1];
    const float* beta  = (const float*)d_in[2];
    const float* cw    = (const float*)d_in[3];
    const float* cb    = (const float*)d_in[4];
    float* out = (float*)d_out;

    const int N = in_sizes[0] / 64;
    const int nchunks1 = (N + TILE - 1) / TILE;
    const int nb1 = nchunks1 < P1CTAS ? nchunks1 : P1CTAS;
    const int nchunks3 = (N + CH - 1) / CH;
    const int nb3 = nchunks3 < P3CTAS ? nchunks3 : P3CTAS;

    cudaFuncSetAttribute(k_pass1, cudaFuncAttributeMaxDynamicSharedMemorySize, P1_SMEM);
    cudaFuncSetAttribute(k_pass3, cudaFuncAttributeMaxDynamicSharedMemorySize, P3_SMEM);

    k_pass1<<<nb1, NTHR, P1_SMEM>>>(x, N, nchunks1);
    k_reduce<<<(PART_STRIDE + 255) / 256, 256>>>(nb1);
    k_pass2<<<1, 64>>>(gamma, beta, cw, cb, (float)N);
    k_pass3<<<nb3, NTHR, P3_SMEM>>>(x, out, N, nchunks3);
}